// round 1
// baseline (speedup 1.0000x reference)
#include <cuda_runtime.h>
#include <math.h>

// ---------------- problem constants ----------------
#define NB   32
#define IBND 103
#define HWD  256
#define PCH  16
#define RB   8
#define DIM  192
#define NTOK 256
#define NROW (NB*NTOK)      // 8192
#define KSC  24
#define KPC  24
#define NC   9
#define FFH  384
#define TAUV (0.07f + 1e-8f)

// ---------------- device scratch (no allocation allowed) ----------------
__device__ __align__(256) float g_dw  [NB*RB*NTOK];
__device__ __align__(256) float g_tok [NROW*DIM];
__device__ __align__(256) float g_xb  [NROW*DIM];
__device__ __align__(256) float g_xn  [NROW*DIM];
__device__ __align__(256) float g_h   [NROW*128];
__device__ __align__(256) float g_rl  [NROW*48];
__device__ __align__(256) float g_cat [NROW*200];
__device__ __align__(256) float g_keys[NROW*DIM];
__device__ __align__(256) float g_q   [NROW*DIM];
__device__ __align__(256) float g_v   [NROW*DIM];
__device__ __align__(256) float g_kv  [NB*DIM*DIM];
__device__ __align__(256) float g_ff  [NROW*FFH];

__device__ __forceinline__ float geluf(float x) {
    return 0.5f * x * (1.0f + erff(x * 0.70710678118654752440f));
}

// ============================================================
// Kernel 1: fused band-reduction conv + depthwise PxP patch conv
//   dw[b,c,i,j] = sum_ib band_w[c,ib] * (sum_pq x[b,ib,16i+p,16j+q]*dw_w[c,p,q])
//               + band_b[c] * sum_pq dw_w[c,p,q]
// grid = NB*16 (b,i), block = 512: thread = (w in 0..255, chalf in 0..1)
// conv weights live in registers (64/thread), x rows double-buffered in smem.
// ============================================================
__global__ void __launch_bounds__(512, 1) k_band_dw(
    const float* __restrict__ x, const float* __restrict__ band_w,
    const float* __restrict__ band_b, const float* __restrict__ dw_w,
    float* __restrict__ dwout)
{
    __shared__ float sdw[RB * 256];          // 8KB   dw_w copy (c,p,q)
    __shared__ float sband[RB * IBND];       // 3.3KB band_w copy
    __shared__ float ssum[RB];               // sum_pq dw_w[c]
    __shared__ float xs[2][16 * 256];        // 32KB  double-buffered patch rows

    const int tid = threadIdx.x;
    const int b = blockIdx.x >> 4;
    const int i = blockIdx.x & 15;

    for (int l = tid; l < RB * 256; l += 512)  sdw[l]   = dw_w[l];
    for (int l = tid; l < RB * IBND; l += 512) sband[l] = band_w[l];
    __syncthreads();
    if (tid < RB) {
        float s = 0.f;
        for (int u = 0; u < 256; u++) s += sdw[tid * 256 + u];
        ssum[tid] = s;
    }

    const int w  = tid & 255;     // column within the 256-wide row
    const int ch = tid >> 8;      // 0 -> c 0..3, 1 -> c 4..7
    const int wq = w & 15;        // q within patch
    const int j  = w >> 4;        // patch index along width

    float wt[4][16];
#pragma unroll
    for (int cl = 0; cl < 4; cl++)
#pragma unroll
        for (int p = 0; p < 16; p++)
            wt[cl][p] = sdw[((ch * 4 + cl) * 16 + p) * 16 + wq];
    __syncthreads();

    // cooperative load mapping: each thread moves 8 floats (2x float4)
    const int lin  = tid * 8;
    const int lrow = lin >> 8;
    const int lcol = lin & 255;

    float D[4] = {0.f, 0.f, 0.f, 0.f};
    float4 f0, f1;
    {
        const float* px = x + (((size_t)(b * IBND + 0) * HWD + i * 16 + lrow) * HWD + lcol);
        f0 = ((const float4*)px)[0];
        f1 = ((const float4*)px)[1];
    }

    for (int ib = 0; ib < IBND; ib++) {
        float* sdst = &xs[ib & 1][lrow * 256 + lcol];
        ((float4*)sdst)[0] = f0;
        ((float4*)sdst)[1] = f1;
        __syncthreads();

        if (ib + 1 < IBND) {
            const float* px = x + (((size_t)(b * IBND + ib + 1) * HWD + i * 16 + lrow) * HWD + lcol);
            f0 = ((const float4*)px)[0];
            f1 = ((const float4*)px)[1];
        }

        const float* xc = &xs[ib & 1][0];
        float s0 = 0.f, s1 = 0.f, s2 = 0.f, s3 = 0.f;
#pragma unroll
        for (int p = 0; p < 16; p++) {
            float xv = xc[p * 256 + w];
            s0 += xv * wt[0][p];
            s1 += xv * wt[1][p];
            s2 += xv * wt[2][p];
            s3 += xv * wt[3][p];
        }
        const int cb = ch * 4;
        D[0] += sband[(cb + 0) * IBND + ib] * s0;
        D[1] += sband[(cb + 1) * IBND + ib] * s1;
        D[2] += sband[(cb + 2) * IBND + ib] * s2;
        D[3] += sband[(cb + 3) * IBND + ib] * s3;
        __syncthreads();
    }

    // reduce over the 16 q-lanes of each patch (width-16 shuffles)
#pragma unroll
    for (int cl = 0; cl < 4; cl++) {
        float v = D[cl];
        v += __shfl_down_sync(0xffffffffu, v, 8, 16);
        v += __shfl_down_sync(0xffffffffu, v, 4, 16);
        v += __shfl_down_sync(0xffffffffu, v, 2, 16);
        v += __shfl_down_sync(0xffffffffu, v, 1, 16);
        if (wq == 0) {
            int c = ch * 4 + cl;
            dwout[((b * RB + c) * 16 + i) * 16 + j] = v + band_b[c] * ssum[c];
        }
    }
}

// ---------------- 192-thread block reduction helper ----------------
__device__ __forceinline__ float blk_sum_192(float v, float* sb) {
#pragma unroll
    for (int o = 16; o; o >>= 1) v += __shfl_down_sync(0xffffffffu, v, o);
    __syncthreads();                      // protect sb reuse across calls
    if ((threadIdx.x & 31) == 0) sb[threadIdx.x >> 5] = v;
    __syncthreads();
    if (threadIdx.x == 0)
        sb[6] = sb[0] + sb[1] + sb[2] + sb[3] + sb[4] + sb[5];
    __syncthreads();
    return sb[6];
}

// ============================================================
// Kernel 2: pointwise 8->192 conv + LayerNorm; writes tok and xb
// grid = NROW, block = 192
// ============================================================
__global__ void k_pw_ln(const float* __restrict__ dw, const float* __restrict__ pw_w,
                        const float* __restrict__ lw, const float* __restrict__ lb,
                        float* __restrict__ tok, float* __restrict__ xbuf)
{
    const int row = blockIdx.x;
    const int b = row >> 8, n = row & 255;
    const int d = threadIdx.x;
    __shared__ float sdwv[RB];
    __shared__ float sb[8];
    if (d < RB) sdwv[d] = dw[((size_t)b * RB + d) * NTOK + n];
    __syncthreads();
    float t = 0.f;
#pragma unroll
    for (int c = 0; c < RB; c++) t += sdwv[c] * pw_w[d * RB + c];
    float mean = blk_sum_192(t, sb) * (1.f / 192.f);
    float dv = t - mean;
    float var = blk_sum_192(dv * dv, sb) * (1.f / 192.f);
    float o = dv * rsqrtf(var + 1e-5f) * lw[d] + lb[d];
    size_t idx = (size_t)row * DIM + d;
    tok[idx] = o;
    xbuf[idx] = o;
}

// ============================================================
// LayerNorm kernel: grid NROW, block 192
// ============================================================
__global__ void k_ln(const float* __restrict__ xin, float* __restrict__ xout,
                     const float* __restrict__ w, const float* __restrict__ b)
{
    const int row = blockIdx.x, d = threadIdx.x;
    __shared__ float sb[8];
    float v = xin[(size_t)row * DIM + d];
    float mean = blk_sum_192(v, sb) * (1.f / 192.f);
    float dv = v - mean;
    float var = blk_sum_192(dv * dv, sb) * (1.f / 192.f);
    xout[(size_t)row * DIM + d] = dv * rsqrtf(var + 1e-5f) * w[d] + b[d];
}

// ============================================================
// row softmax over 192, in place
// ============================================================
__global__ void k_softmax(float* __restrict__ q)
{
    const int row = blockIdx.x, d = threadIdx.x;
    __shared__ float sb[8];
    size_t idx = (size_t)row * DIM + d;
    float v = q[idx];
    float m = v;
#pragma unroll
    for (int o = 16; o; o >>= 1) m = fmaxf(m, __shfl_down_sync(0xffffffffu, m, o));
    if ((d & 31) == 0) sb[d >> 5] = m;
    __syncthreads();
    if (d == 0) {
        float t = sb[0];
        for (int u = 1; u < 6; u++) t = fmaxf(t, sb[u]);
        sb[6] = t;
    }
    __syncthreads();
    float e = expf(v - sb[6]);
    float s = blk_sum_192(e, sb);
    q[idx] = e / s;
}

// ============================================================
// router top-2 + gates + prototype mixing -> cat[row, 200]
// grid NROW, block 192
// ============================================================
__global__ void k_mix(const float* __restrict__ rl, const float* __restrict__ spec_proto,
                      const float* __restrict__ spat_proto, float* __restrict__ cat)
{
    const int row = blockIdx.x;
    const int d = threadIdx.x;
    __shared__ float srl[48];
    __shared__ float sg[4];
    __shared__ int   sidx[4];
    if (d < 48) srl[d] = rl[(size_t)row * 48 + d];
    __syncthreads();
    if (d < 2) {
        const float* base = srl + d * 24;
        float m1 = -1e30f; int i1 = 0;
        for (int k = 0; k < 24; k++) if (base[k] > m1) { m1 = base[k]; i1 = k; }
        float m2 = -1e30f; int i2 = 0;
        for (int k = 0; k < 24; k++) if (k != i1 && base[k] > m2) { m2 = base[k]; i2 = k; }
        float e  = expf((m2 - m1) / TAUV);
        float iv = 1.f / (1.f + e);
        sg[d * 2] = iv; sg[d * 2 + 1] = e * iv;
        sidx[d * 2] = i1; sidx[d * 2 + 1] = i2;
    }
    __syncthreads();
    float* crow = cat + (size_t)row * 200;
    if (d < RB)
        crow[d] = sg[0] * spec_proto[sidx[0] * RB + d] + sg[1] * spec_proto[sidx[1] * RB + d];
    crow[8 + d] = sg[2] * spat_proto[sidx[2] * DIM + d] + sg[3] * spat_proto[sidx[3] * DIM + d];
}

// ============================================================
// generic fp32 GEMM: C = A(MxK) @ B(KxN), optional batch (blockIdx.z)
// tiles: 128x64, BK=16, 256 threads, 8x4 per thread
// EPI: 0 store, 1 +bias, 2 gelu(+bias), 3 C += acc*scale, 4 C += (acc+bias)*scale
// ============================================================
template <int EPI>
__global__ void __launch_bounds__(256) gemm_k(
    const float* __restrict__ A, const float* __restrict__ B,
    float* __restrict__ C, const float* __restrict__ bias,
    const float* __restrict__ scale,
    int M, int N, int K, long sA, long sB, long sC)
{
    __shared__ float As[16][132];   // [k][m], padded
    __shared__ float Bs[16][64];    // [k][n]

    const long bz = blockIdx.z;
    A += bz * sA; B += bz * sB; C += bz * sC;
    const int m0 = blockIdx.y * 128, n0 = blockIdx.x * 64;
    const int tid = threadIdx.x;
    const int ar = tid >> 1, ac = (tid & 1) * 8;
    const int br = tid >> 4, bc = (tid & 15) * 4;
    const int ty = tid >> 4, tx = tid & 15;

    float acc[8][4];
#pragma unroll
    for (int i = 0; i < 8; i++)
#pragma unroll
        for (int jj = 0; jj < 4; jj++) acc[i][jj] = 0.f;

    for (int k0 = 0; k0 < K; k0 += 16) {
        // --- load A tile (transpose into As[k][m]) ---
        const int arow = m0 + ar;
#pragma unroll
        for (int h = 0; h < 2; h++) {
            int kc = k0 + ac + h * 4;
            float4 t = {0.f, 0.f, 0.f, 0.f};
            if (arow < M) {
                if (kc + 3 < K) t = *(const float4*)(A + (size_t)arow * K + kc);
                else {
                    float* tp = (float*)&t;
                    for (int u = 0; u < 4; u++)
                        if (kc + u < K) tp[u] = A[(size_t)arow * K + kc + u];
                }
            }
            As[ac + h * 4 + 0][ar] = t.x;
            As[ac + h * 4 + 1][ar] = t.y;
            As[ac + h * 4 + 2][ar] = t.z;
            As[ac + h * 4 + 3][ar] = t.w;
        }
        // --- load B tile ---
        {
            float4 t = {0.f, 0.f, 0.f, 0.f};
            int krow = k0 + br, bcol = n0 + bc;
            if (krow < K) {
                if (bcol + 3 < N) t = *(const float4*)(B + (size_t)krow * N + bcol);
                else {
                    float* tp = (float*)&t;
                    for (int u = 0; u < 4; u++)
                        if (bcol + u < N) tp[u] = B[(size_t)krow * N + bcol + u];
                }
            }
            *(float4*)&Bs[br][bc] = t;
        }
        __syncthreads();
#pragma unroll
        for (int kk = 0; kk < 16; kk++) {
            float4 a0 = *(const float4*)&As[kk][ty * 8];
            float4 a1 = *(const float4*)&As[kk][ty * 8 + 4];
            float4 b0 = *(const float4*)&Bs[kk][tx * 4];
            float am[8] = {a0.x, a0.y, a0.z, a0.w, a1.x, a1.y, a1.z, a1.w};
            float bm[4] = {b0.x, b0.y, b0.z, b0.w};
#pragma unroll
            for (int i = 0; i < 8; i++)
#pragma unroll
                for (int jj = 0; jj < 4; jj++) acc[i][jj] += am[i] * bm[jj];
        }
        __syncthreads();
    }

#pragma unroll
    for (int i = 0; i < 8; i++) {
        int row = m0 + ty * 8 + i;
        if (row >= M) continue;
#pragma unroll
        for (int jj = 0; jj < 4; jj++) {
            int col = n0 + tx * 4 + jj;
            if (col >= N) continue;
            float v = acc[i][jj];
            size_t idx = (size_t)row * N + col;
            if (EPI == 0)      C[idx] = v;
            else if (EPI == 1) C[idx] = v + bias[col];
            else if (EPI == 2) C[idx] = geluf(v + bias[col]);
            else if (EPI == 3) C[idx] = C[idx] + v * scale[col];
            else if (EPI == 4) C[idx] = C[idx] + (v + bias[col]) * scale[col];
        }
    }
}

// ============================================================
// batched C = A^T @ B : A is KxM, B is KxN (per batch). 64x64 tiles, 4x4/thread.
// used for KV[b] = keys[b]^T @ v[b]
// ============================================================
__global__ void __launch_bounds__(256) gemm_tn_k(
    const float* __restrict__ A, const float* __restrict__ B, float* __restrict__ C,
    int M, int N, int K, long sA, long sB, long sC)
{
    __shared__ float As[16][64];
    __shared__ float Bs[16][64];
    const long bz = blockIdx.z;
    A += bz * sA; B += bz * sB; C += bz * sC;
    const int m0 = blockIdx.y * 64, n0 = blockIdx.x * 64;
    const int tid = threadIdx.x;
    const int br = tid >> 4, bc = (tid & 15) * 4;
    const int ty = tid >> 4, tx = tid & 15;

    float acc[4][4];
#pragma unroll
    for (int i = 0; i < 4; i++)
#pragma unroll
        for (int jj = 0; jj < 4; jj++) acc[i][jj] = 0.f;

    for (int k0 = 0; k0 < K; k0 += 16) {
        float4 av = {0.f, 0.f, 0.f, 0.f}, bv = {0.f, 0.f, 0.f, 0.f};
        int krow = k0 + br;
        if (krow < K && m0 + bc + 3 < M) av = *(const float4*)(A + (size_t)krow * M + m0 + bc);
        if (krow < K && n0 + bc + 3 < N) bv = *(const float4*)(B + (size_t)krow * N + n0 + bc);
        *(float4*)&As[br][bc] = av;
        *(float4*)&Bs[br][bc] = bv;
        __syncthreads();
#pragma unroll
        for (int kk = 0; kk < 16; kk++) {
            float4 a = *(const float4*)&As[kk][ty * 4];
            float4 b = *(const float4*)&Bs[kk][tx * 4];
            float am[4] = {a.x, a.y, a.z, a.w};
            float bm[4] = {b.x, b.y, b.z, b.w};
#pragma unroll
            for (int i = 0; i < 4; i++)
#pragma unroll
                for (int jj = 0; jj < 4; jj++) acc[i][jj] += am[i] * bm[jj];
        }
        __syncthreads();
    }
#pragma unroll
    for (int i = 0; i < 4; i++) {
        int row = m0 + ty * 4 + i;
        if (row >= M) continue;
#pragma unroll
        for (int jj = 0; jj < 4; jj++) {
            int col = n0 + tx * 4 + jj;
            if (col < N) C[(size_t)row * N + col] = acc[i][jj];
        }
    }
}

// ============================================================
// final: feat = LN(mean_n xb), out = feat @ head_w + head_b
// grid NB, block 192
// ============================================================
__global__ void k_final(const float* __restrict__ xb,
                        const float* __restrict__ lw, const float* __restrict__ lb,
                        const float* __restrict__ hw, const float* __restrict__ hb,
                        float* __restrict__ out)
{
    const int b = blockIdx.x, d = threadIdx.x;
    __shared__ float sfeat[DIM];
    __shared__ float sb[8];
    const float* base = xb + (size_t)b * NTOK * DIM;
    float acc = 0.f;
    for (int n = 0; n < NTOK; n++) acc += base[n * DIM + d];
    float m = acc * (1.f / 256.f);
    float mean = blk_sum_192(m, sb) * (1.f / 192.f);
    float dv = m - mean;
    float var = blk_sum_192(dv * dv, sb) * (1.f / 192.f);
    sfeat[d] = dv * rsqrtf(var + 1e-5f) * lw[d] + lb[d];
    __syncthreads();
    if (d < NC) {
        float o = hb[d];
        for (int e = 0; e < DIM; e++) o += sfeat[e] * hw[e * NC + d];
        out[b * NC + d] = o;
    }
}

// ============================================================
extern "C" void kernel_launch(void* const* d_in, const int* in_sizes, int n_in,
                              void* d_out, int out_size)
{
    const float* x        = (const float*)d_in[0];
    const float* band_w   = (const float*)d_in[1];
    const float* band_b   = (const float*)d_in[2];
    const float* dw_w     = (const float*)d_in[3];
    const float* pw_w     = (const float*)d_in[4];
    const float* pe_ln_w  = (const float*)d_in[5];
    const float* pe_ln_b  = (const float*)d_in[6];
    const float* spec_pr  = (const float*)d_in[7];
    const float* spat_pr  = (const float*)d_in[8];
    const float* r1_w     = (const float*)d_in[9];
    const float* r1_b     = (const float*)d_in[10];
    const float* r2_w     = (const float*)d_in[11];
    const float* r2_b     = (const float*)d_in[12];
    const float* key_w    = (const float*)d_in[13];
    const float* pos_bias = (const float*)d_in[14];
    const float* bln_w    = (const float*)d_in[15];
    const float* bln_b    = (const float*)d_in[16];
    const float* bq_w     = (const float*)d_in[17];
    const float* bv_w     = (const float*)d_in[18];
    const float* bf1_w    = (const float*)d_in[19];
    const float* bf1_b    = (const float*)d_in[20];
    const float* bf2_w    = (const float*)d_in[21];
    const float* bf2_b    = (const float*)d_in[22];
    const float* bg1      = (const float*)d_in[23];
    const float* bg2      = (const float*)d_in[24];
    const float* fin_ln_w = (const float*)d_in[25];
    const float* fin_ln_b = (const float*)d_in[26];
    const float* head_w   = (const float*)d_in[27];
    const float* head_b   = (const float*)d_in[28];
    float* out = (float*)d_out;

    float *dw, *tok, *xb, *xn, *h, *rl, *cat, *keys, *q, *v, *kv, *ff;
    cudaGetSymbolAddress((void**)&dw,   g_dw);
    cudaGetSymbolAddress((void**)&tok,  g_tok);
    cudaGetSymbolAddress((void**)&xb,   g_xb);
    cudaGetSymbolAddress((void**)&xn,   g_xn);
    cudaGetSymbolAddress((void**)&h,    g_h);
    cudaGetSymbolAddress((void**)&rl,   g_rl);
    cudaGetSymbolAddress((void**)&cat,  g_cat);
    cudaGetSymbolAddress((void**)&keys, g_keys);
    cudaGetSymbolAddress((void**)&q,    g_q);
    cudaGetSymbolAddress((void**)&v,    g_v);
    cudaGetSymbolAddress((void**)&kv,   g_kv);
    cudaGetSymbolAddress((void**)&ff,   g_ff);

    // 1. fused band + depthwise conv
    k_band_dw<<<NB * 16, 512>>>(x, band_w, band_b, dw_w, dw);
    // 2. pointwise conv + LN -> tok, xb
    k_pw_ln<<<NROW, DIM>>>(dw, pw_w, pe_ln_w, pe_ln_b, tok, xb);
    // 3. router MLP
    gemm_k<2><<<dim3(2, 64), 256>>>(tok, r1_w, h, r1_b, nullptr, NROW, 128, DIM, 0, 0, 0);
    gemm_k<1><<<dim3(1, 64), 256>>>(h, r2_w, rl, r2_b, nullptr, NROW, 48, 128, 0, 0, 0);
    // 4. top-2 gates + prototype mix -> cat[.,200]
    k_mix<<<NROW, DIM>>>(rl, spec_pr, spat_pr, cat);
    // 5. keys = cat @ key_w + pos_bias
    gemm_k<1><<<dim3(3, 64), 256>>>(cat, key_w, keys, pos_bias, nullptr, NROW, DIM, 200, 0, 0, 0);

    const long sTok = (long)NTOK * DIM;   // per-batch stride for (N,DIM) tensors
    const long sKV  = (long)DIM * DIM;

    for (int i = 0; i < 3; i++) {
        const float* lwi = bln_w + i * DIM;
        const float* lbi = bln_b + i * DIM;
        // attn branch
        k_ln<<<NROW, DIM>>>(xb, xn, lwi, lbi);
        gemm_k<0><<<dim3(3, 64), 256>>>(xn, bq_w + (size_t)i * DIM * DIM, q, nullptr, nullptr, NROW, DIM, DIM, 0, 0, 0);
        gemm_k<0><<<dim3(3, 64), 256>>>(xn, bv_w + (size_t)i * DIM * DIM, v, nullptr, nullptr, NROW, DIM, DIM, 0, 0, 0);
        k_softmax<<<NROW, DIM>>>(q);
        gemm_tn_k<<<dim3(3, 3, NB), 256>>>(keys, v, kv, DIM, DIM, NTOK, sTok, sTok, sKV);
        gemm_k<3><<<dim3(3, 2, NB), 256>>>(q, kv, xb, nullptr, bg1 + i * DIM, NTOK, DIM, DIM, sTok, sKV, sTok);
        // ffn branch
        k_ln<<<NROW, DIM>>>(xb, xn, lwi, lbi);
        gemm_k<2><<<dim3(6, 64), 256>>>(xn, bf1_w + (size_t)i * DIM * FFH, ff, bf1_b + i * FFH, nullptr, NROW, FFH, DIM, 0, 0, 0);
        gemm_k<4><<<dim3(3, 64), 256>>>(ff, bf2_w + (size_t)i * FFH * DIM, xb, bf2_b + i * DIM, bg2 + i * DIM, NROW, DIM, FFH, 0, 0, 0);
    }

    // final pooling + LN + head
    k_final<<<NB, DIM>>>(xb, fin_ln_w, fin_ln_b, head_w, head_b, out);

    (void)in_sizes; (void)n_in; (void)out_size;
}

// round 2
// speedup vs baseline: 1.1345x; 1.1345x over previous
#include <cuda_runtime.h>
#include <math.h>
#include <stdint.h>

// ---------------- problem constants ----------------
#define NB   32
#define IBND 103
#define HWD  256
#define PCH  16
#define RB   8
#define DIM  192
#define NTOK 256
#define NROW (NB*NTOK)      // 8192
#define KSC  24
#define KPC  24
#define NC   9
#define FFH  384
#define TAUV (0.07f + 1e-8f)

// ---------------- device scratch (no allocation allowed) ----------------
__device__ __align__(256) float g_dw  [NB*RB*NTOK];
__device__ __align__(256) float g_tok [NROW*DIM];
__device__ __align__(256) float g_xb  [NROW*DIM];
__device__ __align__(256) float g_xn  [NROW*DIM];
__device__ __align__(256) float g_h   [NROW*128];
__device__ __align__(256) float g_rl  [NROW*48];
__device__ __align__(256) float g_cat [NROW*200];
__device__ __align__(256) float g_keys[NROW*DIM];
__device__ __align__(256) float g_q   [NROW*DIM];
__device__ __align__(256) float g_v   [NROW*DIM];
__device__ __align__(256) float g_kv  [NB*DIM*DIM];
__device__ __align__(256) float g_ff  [NROW*FFH];

__device__ __forceinline__ float geluf(float x) {
    return 0.5f * x * (1.0f + erff(x * 0.70710678118654752440f));
}

__device__ __forceinline__ uint32_t to_tf32(float x) {
    uint32_t u;
    asm("cvt.rna.tf32.f32 %0, %1;" : "=r"(u) : "f"(x));
    return u;
}

__device__ __forceinline__ void mma_tf32(float* c, const uint32_t* a, const uint32_t* b) {
    asm volatile(
        "mma.sync.aligned.m16n8k8.row.col.f32.tf32.tf32.f32 "
        "{%0,%1,%2,%3}, {%4,%5,%6,%7}, {%8,%9}, {%0,%1,%2,%3};\n"
        : "+f"(c[0]), "+f"(c[1]), "+f"(c[2]), "+f"(c[3])
        : "r"(a[0]), "r"(a[1]), "r"(a[2]), "r"(a[3]), "r"(b[0]), "r"(b[1]));
}

// ============================================================
// Kernel 1: fused band-reduction conv + depthwise PxP patch conv (fp32 exact)
// ============================================================
__global__ void __launch_bounds__(512, 1) k_band_dw(
    const float* __restrict__ x, const float* __restrict__ band_w,
    const float* __restrict__ band_b, const float* __restrict__ dw_w,
    float* __restrict__ dwout)
{
    __shared__ float sdw[RB * 256];
    __shared__ float sband[RB * IBND];
    __shared__ float ssum[RB];
    __shared__ float xs[2][16 * 256];

    const int tid = threadIdx.x;
    const int b = blockIdx.x >> 4;
    const int i = blockIdx.x & 15;

    for (int l = tid; l < RB * 256; l += 512)  sdw[l]   = dw_w[l];
    for (int l = tid; l < RB * IBND; l += 512) sband[l] = band_w[l];
    __syncthreads();
    if (tid < RB) {
        float s = 0.f;
        for (int u = 0; u < 256; u++) s += sdw[tid * 256 + u];
        ssum[tid] = s;
    }

    const int w  = tid & 255;
    const int ch = tid >> 8;
    const int wq = w & 15;
    const int j  = w >> 4;

    float wt[4][16];
#pragma unroll
    for (int cl = 0; cl < 4; cl++)
#pragma unroll
        for (int p = 0; p < 16; p++)
            wt[cl][p] = sdw[((ch * 4 + cl) * 16 + p) * 16 + wq];
    __syncthreads();

    const int lin  = tid * 8;
    const int lrow = lin >> 8;
    const int lcol = lin & 255;

    float D[4] = {0.f, 0.f, 0.f, 0.f};
    float4 f0, f1;
    {
        const float* px = x + (((size_t)(b * IBND + 0) * HWD + i * 16 + lrow) * HWD + lcol);
        f0 = ((const float4*)px)[0];
        f1 = ((const float4*)px)[1];
    }

    for (int ib = 0; ib < IBND; ib++) {
        float* sdst = &xs[ib & 1][lrow * 256 + lcol];
        ((float4*)sdst)[0] = f0;
        ((float4*)sdst)[1] = f1;
        __syncthreads();

        if (ib + 1 < IBND) {
            const float* px = x + (((size_t)(b * IBND + ib + 1) * HWD + i * 16 + lrow) * HWD + lcol);
            f0 = ((const float4*)px)[0];
            f1 = ((const float4*)px)[1];
        }

        const float* xc = &xs[ib & 1][0];
        float s0 = 0.f, s1 = 0.f, s2 = 0.f, s3 = 0.f;
#pragma unroll
        for (int p = 0; p < 16; p++) {
            float xv = xc[p * 256 + w];
            s0 += xv * wt[0][p];
            s1 += xv * wt[1][p];
            s2 += xv * wt[2][p];
            s3 += xv * wt[3][p];
        }
        const int cb = ch * 4;
        D[0] += sband[(cb + 0) * IBND + ib] * s0;
        D[1] += sband[(cb + 1) * IBND + ib] * s1;
        D[2] += sband[(cb + 2) * IBND + ib] * s2;
        D[3] += sband[(cb + 3) * IBND + ib] * s3;
        __syncthreads();
    }

#pragma unroll
    for (int cl = 0; cl < 4; cl++) {
        float v = D[cl];
        v += __shfl_down_sync(0xffffffffu, v, 8, 16);
        v += __shfl_down_sync(0xffffffffu, v, 4, 16);
        v += __shfl_down_sync(0xffffffffu, v, 2, 16);
        v += __shfl_down_sync(0xffffffffu, v, 1, 16);
        if (wq == 0) {
            int c = ch * 4 + cl;
            dwout[((b * RB + c) * 16 + i) * 16 + j] = v + band_b[c] * ssum[c];
        }
    }
}

// ---------------- 192-thread block reduction helper ----------------
__device__ __forceinline__ float blk_sum_192(float v, float* sb) {
#pragma unroll
    for (int o = 16; o; o >>= 1) v += __shfl_down_sync(0xffffffffu, v, o);
    __syncthreads();
    if ((threadIdx.x & 31) == 0) sb[threadIdx.x >> 5] = v;
    __syncthreads();
    if (threadIdx.x == 0)
        sb[6] = sb[0] + sb[1] + sb[2] + sb[3] + sb[4] + sb[5];
    __syncthreads();
    return sb[6];
}

// ============================================================
// Kernel 2: pointwise 8->192 conv + LayerNorm
// ============================================================
__global__ void k_pw_ln(const float* __restrict__ dw, const float* __restrict__ pw_w,
                        const float* __restrict__ lw, const float* __restrict__ lb,
                        float* __restrict__ tok, float* __restrict__ xbuf)
{
    const int row = blockIdx.x;
    const int b = row >> 8, n = row & 255;
    const int d = threadIdx.x;
    __shared__ float sdwv[RB];
    __shared__ float sb[8];
    if (d < RB) sdwv[d] = dw[((size_t)b * RB + d) * NTOK + n];
    __syncthreads();
    float t = 0.f;
#pragma unroll
    for (int c = 0; c < RB; c++) t += sdwv[c] * pw_w[d * RB + c];
    float mean = blk_sum_192(t, sb) * (1.f / 192.f);
    float dv = t - mean;
    float var = blk_sum_192(dv * dv, sb) * (1.f / 192.f);
    float o = dv * rsqrtf(var + 1e-5f) * lw[d] + lb[d];
    size_t idx = (size_t)row * DIM + d;
    tok[idx] = o;
    xbuf[idx] = o;
}

// ============================================================
// LayerNorm: grid NROW, block 192
// ============================================================
__global__ void k_ln(const float* __restrict__ xin, float* __restrict__ xout,
                     const float* __restrict__ w, const float* __restrict__ b)
{
    const int row = blockIdx.x, d = threadIdx.x;
    __shared__ float sb[8];
    float v = xin[(size_t)row * DIM + d];
    float mean = blk_sum_192(v, sb) * (1.f / 192.f);
    float dv = v - mean;
    float var = blk_sum_192(dv * dv, sb) * (1.f / 192.f);
    xout[(size_t)row * DIM + d] = dv * rsqrtf(var + 1e-5f) * w[d] + b[d];
}

// ============================================================
// row softmax over 192, in place
// ============================================================
__global__ void k_softmax(float* __restrict__ q)
{
    const int row = blockIdx.x, d = threadIdx.x;
    __shared__ float sb[8];
    size_t idx = (size_t)row * DIM + d;
    float v = q[idx];
    float m = v;
#pragma unroll
    for (int o = 16; o; o >>= 1) m = fmaxf(m, __shfl_down_sync(0xffffffffu, m, o));
    if ((d & 31) == 0) sb[d >> 5] = m;
    __syncthreads();
    if (d == 0) {
        float t = sb[0];
        for (int u = 1; u < 6; u++) t = fmaxf(t, sb[u]);
        sb[6] = t;
    }
    __syncthreads();
    float e = expf(v - sb[6]);
    float s = blk_sum_192(e, sb);
    q[idx] = e / s;
}

// ============================================================
// router top-2 + gates + prototype mixing -> cat[row, 200]
// ============================================================
__global__ void k_mix(const float* __restrict__ rl, const float* __restrict__ spec_proto,
                      const float* __restrict__ spat_proto, float* __restrict__ cat)
{
    const int row = blockIdx.x;
    const int d = threadIdx.x;
    __shared__ float srl[48];
    __shared__ float sg[4];
    __shared__ int   sidx[4];
    if (d < 48) srl[d] = rl[(size_t)row * 48 + d];
    __syncthreads();
    if (d < 2) {
        const float* base = srl + d * 24;
        float m1 = -1e30f; int i1 = 0;
        for (int k = 0; k < 24; k++) if (base[k] > m1) { m1 = base[k]; i1 = k; }
        float m2 = -1e30f; int i2 = 0;
        for (int k = 0; k < 24; k++) if (k != i1 && base[k] > m2) { m2 = base[k]; i2 = k; }
        float e  = expf((m2 - m1) / TAUV);
        float iv = 1.f / (1.f + e);
        sg[d * 2] = iv; sg[d * 2 + 1] = e * iv;
        sidx[d * 2] = i1; sidx[d * 2 + 1] = i2;
    }
    __syncthreads();
    float* crow = cat + (size_t)row * 200;
    if (d < RB)
        crow[d] = sg[0] * spec_proto[sidx[0] * RB + d] + sg[1] * spec_proto[sidx[1] * RB + d];
    crow[8 + d] = sg[2] * spat_proto[sidx[2] * DIM + d] + sg[3] * spat_proto[sidx[3] * DIM + d];
}

// ============================================================
// exact fp32 FFMA GEMM (kept for the router path only — bit-exact top-k)
// ============================================================
template <int EPI>
__global__ void __launch_bounds__(256) gemm_k(
    const float* __restrict__ A, const float* __restrict__ B,
    float* __restrict__ C, const float* __restrict__ bias,
    const float* __restrict__ scale,
    int M, int N, int K, long sA, long sB, long sC)
{
    __shared__ float As[16][132];
    __shared__ float Bs[16][64];

    const long bz = blockIdx.z;
    A += bz * sA; B += bz * sB; C += bz * sC;
    const int m0 = blockIdx.y * 128, n0 = blockIdx.x * 64;
    const int tid = threadIdx.x;
    const int ar = tid >> 1, ac = (tid & 1) * 8;
    const int br = tid >> 4, bc = (tid & 15) * 4;
    const int ty = tid >> 4, tx = tid & 15;

    float acc[8][4];
#pragma unroll
    for (int i = 0; i < 8; i++)
#pragma unroll
        for (int jj = 0; jj < 4; jj++) acc[i][jj] = 0.f;

    for (int k0 = 0; k0 < K; k0 += 16) {
        const int arow = m0 + ar;
#pragma unroll
        for (int h = 0; h < 2; h++) {
            int kc = k0 + ac + h * 4;
            float4 t = {0.f, 0.f, 0.f, 0.f};
            if (arow < M) {
                if (kc + 3 < K) t = *(const float4*)(A + (size_t)arow * K + kc);
                else {
                    float* tp = (float*)&t;
                    for (int u = 0; u < 4; u++)
                        if (kc + u < K) tp[u] = A[(size_t)arow * K + kc + u];
                }
            }
            As[ac + h * 4 + 0][ar] = t.x;
            As[ac + h * 4 + 1][ar] = t.y;
            As[ac + h * 4 + 2][ar] = t.z;
            As[ac + h * 4 + 3][ar] = t.w;
        }
        {
            float4 t = {0.f, 0.f, 0.f, 0.f};
            int krow = k0 + br, bcol = n0 + bc;
            if (krow < K) {
                if (bcol + 3 < N) t = *(const float4*)(B + (size_t)krow * N + bcol);
                else {
                    float* tp = (float*)&t;
                    for (int u = 0; u < 4; u++)
                        if (bcol + u < N) tp[u] = B[(size_t)krow * N + bcol + u];
                }
            }
            *(float4*)&Bs[br][bc] = t;
        }
        __syncthreads();
#pragma unroll
        for (int kk = 0; kk < 16; kk++) {
            float4 a0 = *(const float4*)&As[kk][ty * 8];
            float4 a1 = *(const float4*)&As[kk][ty * 8 + 4];
            float4 b0 = *(const float4*)&Bs[kk][tx * 4];
            float am[8] = {a0.x, a0.y, a0.z, a0.w, a1.x, a1.y, a1.z, a1.w};
            float bm[4] = {b0.x, b0.y, b0.z, b0.w};
#pragma unroll
            for (int i = 0; i < 8; i++)
#pragma unroll
                for (int jj = 0; jj < 4; jj++) acc[i][jj] += am[i] * bm[jj];
        }
        __syncthreads();
    }

#pragma unroll
    for (int i = 0; i < 8; i++) {
        int row = m0 + ty * 8 + i;
        if (row >= M) continue;
#pragma unroll
        for (int jj = 0; jj < 4; jj++) {
            int col = n0 + tx * 4 + jj;
            if (col >= N) continue;
            float v = acc[i][jj];
            size_t idx = (size_t)row * N + col;
            if (EPI == 0)      C[idx] = v;
            else if (EPI == 1) C[idx] = v + bias[col];
            else if (EPI == 2) C[idx] = geluf(v + bias[col]);
            else if (EPI == 3) C[idx] = C[idx] + v * scale[col];
            else if (EPI == 4) C[idx] = C[idx] + (v + bias[col]) * scale[col];
        }
    }
}

// ============================================================
// tf32 tensor-core GEMM: C = A @ B (+epilogue), optional batch (blockIdx.z)
// TRANSA=0: A is MxK row-major.  TRANSA=1: A is KxM row-major (computes A^T@B).
// BM=128, BN=64, BK=32, 256 threads = 8 warps (4m x 2n), warp tile 32x32.
// EPI: 0 store, 1 +bias, 2 gelu(+bias), 3 C += acc*scale, 4 C += (acc+bias)*scale
// ============================================================
template <int EPI, int TRANSA>
__global__ void __launch_bounds__(256) mma_gemm(
    const float* __restrict__ A, const float* __restrict__ B,
    float* __restrict__ C, const float* __restrict__ bias,
    const float* __restrict__ scale,
    int M, int N, int K, long sAs, long sBs, long sCs)
{
    // TRANSA=0: sA layout [m][36] (4608 floats). TRANSA=1: [k][136] (4352 floats).
    __shared__ float sA[4608];
    __shared__ float sB[32 * 72];

    const long bz = blockIdx.z;
    A += bz * sAs; B += bz * sBs; C += bz * sCs;
    const int m0 = blockIdx.y * 128, n0 = blockIdx.x * 64;
    const int tid = threadIdx.x;
    const int warp = tid >> 5, lane = tid & 31;
    const int grp = lane >> 2, tig = lane & 3;
    const int wm = warp >> 1, wn = warp & 1;

    float acc[2][4][4];
#pragma unroll
    for (int mt = 0; mt < 2; mt++)
#pragma unroll
        for (int nt = 0; nt < 4; nt++)
#pragma unroll
            for (int e = 0; e < 4; e++) acc[mt][nt][e] = 0.f;

    for (int k0 = 0; k0 < K; k0 += 32) {
        // ---- load A tile ----
        if (TRANSA == 0) {
            // sA[m][kpad36], m in [0,128), k in [0,32)
#pragma unroll
            for (int it = 0; it < 4; it++) {
                int id = tid + it * 256;          // 0..1023
                int m = id >> 3, k4 = (id & 7) * 4;
                int gm = m0 + m, gk = k0 + k4;
                float4 t = make_float4(0.f, 0.f, 0.f, 0.f);
                if (gm < M) {
                    if (gk + 3 < K) t = *(const float4*)(A + (size_t)gm * K + gk);
                    else {
                        float* tp = (float*)&t;
#pragma unroll
                        for (int u = 0; u < 4; u++)
                            if (gk + u < K) tp[u] = A[(size_t)gm * K + gk + u];
                    }
                }
                uint4 c;
                c.x = to_tf32(t.x); c.y = to_tf32(t.y);
                c.z = to_tf32(t.z); c.w = to_tf32(t.w);
                *(uint4*)&sA[m * 36 + k4] = c;
            }
        } else {
            // sA[k][mpad136], k in [0,32), m in [0,128); A is KxM (lda = M)
#pragma unroll
            for (int it = 0; it < 4; it++) {
                int id = tid + it * 256;          // 0..1023
                int k = id >> 5, m4 = (id & 31) * 4;
                int gk = k0 + k, gm = m0 + m4;
                float4 t = make_float4(0.f, 0.f, 0.f, 0.f);
                if (gk < K) {
                    if (gm + 3 < M) t = *(const float4*)(A + (size_t)gk * M + gm);
                    else {
                        float* tp = (float*)&t;
#pragma unroll
                        for (int u = 0; u < 4; u++)
                            if (gm + u < M) tp[u] = A[(size_t)gk * M + gm + u];
                    }
                }
                uint4 c;
                c.x = to_tf32(t.x); c.y = to_tf32(t.y);
                c.z = to_tf32(t.z); c.w = to_tf32(t.w);
                *(uint4*)&sA[k * 136 + m4] = c;
            }
        }
        // ---- load B tile: sB[k][npad72] ----
#pragma unroll
        for (int it = 0; it < 2; it++) {
            int id = tid + it * 256;              // 0..511
            int k = id >> 4, n4 = (id & 15) * 4;
            int gk = k0 + k, gn = n0 + n4;
            float4 t = make_float4(0.f, 0.f, 0.f, 0.f);
            if (gk < K) {
                if (gn + 3 < N) t = *(const float4*)(B + (size_t)gk * N + gn);
                else {
                    float* tp = (float*)&t;
#pragma unroll
                    for (int u = 0; u < 4; u++)
                        if (gn + u < N) tp[u] = B[(size_t)gk * N + gn + u];
                }
            }
            uint4 c;
            c.x = to_tf32(t.x); c.y = to_tf32(t.y);
            c.z = to_tf32(t.z); c.w = to_tf32(t.w);
            *(uint4*)&sB[k * 72 + n4] = c;
        }
        __syncthreads();

        // ---- compute: 4 k-steps of 8 ----
#pragma unroll
        for (int ks = 0; ks < 4; ks++) {
            const int kb = ks * 8;
            uint32_t a[2][4], b[4][2];
#pragma unroll
            for (int mt = 0; mt < 2; mt++) {
                int mr = wm * 32 + mt * 16 + grp;
                if (TRANSA == 0) {
                    a[mt][0] = __float_as_uint(sA[(mr)     * 36 + kb + tig]);
                    a[mt][1] = __float_as_uint(sA[(mr + 8) * 36 + kb + tig]);
                    a[mt][2] = __float_as_uint(sA[(mr)     * 36 + kb + tig + 4]);
                    a[mt][3] = __float_as_uint(sA[(mr + 8) * 36 + kb + tig + 4]);
                } else {
                    a[mt][0] = __float_as_uint(sA[(kb + tig)     * 136 + mr]);
                    a[mt][1] = __float_as_uint(sA[(kb + tig)     * 136 + mr + 8]);
                    a[mt][2] = __float_as_uint(sA[(kb + tig + 4) * 136 + mr]);
                    a[mt][3] = __float_as_uint(sA[(kb + tig + 4) * 136 + mr + 8]);
                }
            }
#pragma unroll
            for (int nt = 0; nt < 4; nt++) {
                int nc = wn * 32 + nt * 8 + grp;
                b[nt][0] = __float_as_uint(sB[(kb + tig)     * 72 + nc]);
                b[nt][1] = __float_as_uint(sB[(kb + tig + 4) * 72 + nc]);
            }
#pragma unroll
            for (int mt = 0; mt < 2; mt++)
#pragma unroll
                for (int nt = 0; nt < 4; nt++)
                    mma_tf32(acc[mt][nt], a[mt], b[nt]);
        }
        __syncthreads();
    }

    // ---- epilogue ----
#pragma unroll
    for (int mt = 0; mt < 2; mt++) {
        int r0 = m0 + wm * 32 + mt * 16 + grp;
#pragma unroll
        for (int nt = 0; nt < 4; nt++) {
            int c0 = n0 + wn * 32 + nt * 8 + tig * 2;
            const float* ap = acc[mt][nt];
#pragma unroll
            for (int e = 0; e < 4; e++) {
                int row = r0 + (e >= 2 ? 8 : 0);
                int col = c0 + (e & 1);
                if (row >= M || col >= N) continue;
                float v = ap[e];
                size_t idx = (size_t)row * N + col;
                if (EPI == 0)      C[idx] = v;
                else if (EPI == 1) C[idx] = v + bias[col];
                else if (EPI == 2) C[idx] = geluf(v + bias[col]);
                else if (EPI == 3) C[idx] = C[idx] + v * scale[col];
                else if (EPI == 4) C[idx] = C[idx] + (v + bias[col]) * scale[col];
            }
        }
    }
}

// ============================================================
// final: feat = LN(mean_n xb), out = feat @ head_w + head_b
// ============================================================
__global__ void k_final(const float* __restrict__ xb,
                        const float* __restrict__ lw, const float* __restrict__ lb,
                        const float* __restrict__ hw, const float* __restrict__ hb,
                        float* __restrict__ out)
{
    const int b = blockIdx.x, d = threadIdx.x;
    __shared__ float sfeat[DIM];
    __shared__ float sb[8];
    const float* base = xb + (size_t)b * NTOK * DIM;
    float acc = 0.f;
    for (int n = 0; n < NTOK; n++) acc += base[n * DIM + d];
    float m = acc * (1.f / 256.f);
    float mean = blk_sum_192(m, sb) * (1.f / 192.f);
    float dv = m - mean;
    float var = blk_sum_192(dv * dv, sb) * (1.f / 192.f);
    sfeat[d] = dv * rsqrtf(var + 1e-5f) * lw[d] + lb[d];
    __syncthreads();
    if (d < NC) {
        float o = hb[d];
        for (int e = 0; e < DIM; e++) o += sfeat[e] * hw[e * NC + d];
        out[b * NC + d] = o;
    }
}

// ============================================================
extern "C" void kernel_launch(void* const* d_in, const int* in_sizes, int n_in,
                              void* d_out, int out_size)
{
    const float* x        = (const float*)d_in[0];
    const float* band_w   = (const float*)d_in[1];
    const float* band_b   = (const float*)d_in[2];
    const float* dw_w     = (const float*)d_in[3];
    const float* pw_w     = (const float*)d_in[4];
    const float* pe_ln_w  = (const float*)d_in[5];
    const float* pe_ln_b  = (const float*)d_in[6];
    const float* spec_pr  = (const float*)d_in[7];
    const float* spat_pr  = (const float*)d_in[8];
    const float* r1_w     = (const float*)d_in[9];
    const float* r1_b     = (const float*)d_in[10];
    const float* r2_w     = (const float*)d_in[11];
    const float* r2_b     = (const float*)d_in[12];
    const float* key_w    = (const float*)d_in[13];
    const float* pos_bias = (const float*)d_in[14];
    const float* bln_w    = (const float*)d_in[15];
    const float* bln_b    = (const float*)d_in[16];
    const float* bq_w     = (const float*)d_in[17];
    const float* bv_w     = (const float*)d_in[18];
    const float* bf1_w    = (const float*)d_in[19];
    const float* bf1_b    = (const float*)d_in[20];
    const float* bf2_w    = (const float*)d_in[21];
    const float* bf2_b    = (const float*)d_in[22];
    const float* bg1      = (const float*)d_in[23];
    const float* bg2      = (const float*)d_in[24];
    const float* fin_ln_w = (const float*)d_in[25];
    const float* fin_ln_b = (const float*)d_in[26];
    const float* head_w   = (const float*)d_in[27];
    const float* head_b   = (const float*)d_in[28];
    float* out = (float*)d_out;

    float *dw, *tok, *xb, *xn, *h, *rl, *cat, *keys, *q, *v, *kv, *ff;
    cudaGetSymbolAddress((void**)&dw,   g_dw);
    cudaGetSymbolAddress((void**)&tok,  g_tok);
    cudaGetSymbolAddress((void**)&xb,   g_xb);
    cudaGetSymbolAddress((void**)&xn,   g_xn);
    cudaGetSymbolAddress((void**)&h,    g_h);
    cudaGetSymbolAddress((void**)&rl,   g_rl);
    cudaGetSymbolAddress((void**)&cat,  g_cat);
    cudaGetSymbolAddress((void**)&keys, g_keys);
    cudaGetSymbolAddress((void**)&q,    g_q);
    cudaGetSymbolAddress((void**)&v,    g_v);
    cudaGetSymbolAddress((void**)&kv,   g_kv);
    cudaGetSymbolAddress((void**)&ff,   g_ff);

    // 1. fused band + depthwise conv
    k_band_dw<<<NB * 16, 512>>>(x, band_w, band_b, dw_w, dw);
    // 2. pointwise conv + LN -> tok, xb
    k_pw_ln<<<NROW, DIM>>>(dw, pw_w, pe_ln_w, pe_ln_b, tok, xb);
    // 3. router MLP (exact fp32 — protects top-k index selection)
    gemm_k<2><<<dim3(2, 64), 256>>>(tok, r1_w, h, r1_b, nullptr, NROW, 128, DIM, 0, 0, 0);
    gemm_k<1><<<dim3(1, 64), 256>>>(h, r2_w, rl, r2_b, nullptr, NROW, 48, 128, 0, 0, 0);
    // 4. top-2 gates + prototype mix -> cat[.,200]
    k_mix<<<NROW, DIM>>>(rl, spec_pr, spat_pr, cat);
    // 5. keys = cat @ key_w + pos_bias   (tf32)
    mma_gemm<1, 0><<<dim3(3, 64), 256>>>(cat, key_w, keys, pos_bias, nullptr, NROW, DIM, 200, 0, 0, 0);

    const long sTok = (long)NTOK * DIM;
    const long sKV  = (long)DIM * DIM;

    for (int i = 0; i < 3; i++) {
        const float* lwi = bln_w + i * DIM;
        const float* lbi = bln_b + i * DIM;
        // attn branch
        k_ln<<<NROW, DIM>>>(xb, xn, lwi, lbi);
        mma_gemm<0, 0><<<dim3(3, 64), 256>>>(xn, bq_w + (size_t)i * DIM * DIM, q, nullptr, nullptr, NROW, DIM, DIM, 0, 0, 0);
        mma_gemm<0, 0><<<dim3(3, 64), 256>>>(xn, bv_w + (size_t)i * DIM * DIM, v, nullptr, nullptr, NROW, DIM, DIM, 0, 0, 0);
        k_softmax<<<NROW, DIM>>>(q);
        // KV[b] = keys[b]^T @ v[b]  (TN path)
        mma_gemm<0, 1><<<dim3(3, 2, NB), 256>>>(keys, v, kv, nullptr, nullptr, DIM, DIM, NTOK, sTok, sTok, sKV);
        // xb += (q_s @ KV) * g1
        mma_gemm<3, 0><<<dim3(3, 2, NB), 256>>>(q, kv, xb, nullptr, bg1 + i * DIM, NTOK, DIM, DIM, sTok, sKV, sTok);
        // ffn branch
        k_ln<<<NROW, DIM>>>(xb, xn, lwi, lbi);
        mma_gemm<2, 0><<<dim3(6, 64), 256>>>(xn, bf1_w + (size_t)i * DIM * FFH, ff, bf1_b + i * FFH, nullptr, NROW, FFH, DIM, 0, 0, 0);
        mma_gemm<4, 0><<<dim3(3, 64), 256>>>(ff, bf2_w + (size_t)i * FFH * DIM, xb, bf2_b + i * DIM, bg2 + i * DIM, NROW, DIM, FFH, 0, 0, 0);
    }

    // final pooling + LN + head
    k_final<<<NB, DIM>>>(xb, fin_ln_w, fin_ln_b, head_w, head_b, out);

    (void)in_sizes; (void)n_in; (void)out_size;
}

// round 3
// speedup vs baseline: 1.2904x; 1.1375x over previous
#include <cuda_runtime.h>
#include <math.h>
#include <stdint.h>

// ---------------- problem constants ----------------
#define NB   32
#define IBND 103
#define HWD  256
#define RB   8
#define DIM  192
#define NTOK 256
#define NROW (NB*NTOK)      // 8192
#define NC   9
#define FFH  384
#define TAUV (0.07f + 1e-8f)

// ---------------- device scratch ----------------
__device__ __align__(256) float g_dw  [NB*RB*NTOK];
__device__ __align__(256) float g_tok [NROW*DIM];
__device__ __align__(256) float g_xb  [NROW*DIM];
__device__ __align__(256) float g_h   [NROW*128];
__device__ __align__(256) float g_rl  [NROW*48];
__device__ __align__(256) float g_cat [NROW*200];
__device__ __align__(256) float g_keys[NROW*DIM];
__device__ __align__(256) float g_q   [NROW*DIM];
__device__ __align__(256) float g_v   [NROW*DIM];
__device__ __align__(256) float g_kv  [NB*DIM*DIM];
__device__ __align__(256) float g_ff  [NROW*FFH];
__device__ __align__(256) float g_s0  [NROW];
__device__ __align__(256) float g_s1  [NROW];

__device__ __forceinline__ float geluf(float x) {
    return 0.5f * x * (1.0f + erff(x * 0.70710678118654752440f));
}

__device__ __forceinline__ uint32_t to_tf32(float x) {
    uint32_t u;
    asm("cvt.rna.tf32.f32 %0, %1;" : "=r"(u) : "f"(x));
    return u;
}

__device__ __forceinline__ void mma_tf32(float* c, const uint32_t* a, const uint32_t* b) {
    asm volatile(
        "mma.sync.aligned.m16n8k8.row.col.f32.tf32.tf32.f32 "
        "{%0,%1,%2,%3}, {%4,%5,%6,%7}, {%8,%9}, {%0,%1,%2,%3};\n"
        : "+f"(c[0]), "+f"(c[1]), "+f"(c[2]), "+f"(c[3])
        : "r"(a[0]), "r"(a[1]), "r"(a[2]), "r"(a[3]), "r"(b[0]), "r"(b[1]));
}

// ============================================================
// Kernel 1: fused band-reduction + depthwise 16x16 patch conv (fp32 exact)
// ============================================================
__global__ void __launch_bounds__(512, 1) k_band_dw(
    const float* __restrict__ x, const float* __restrict__ band_w,
    const float* __restrict__ band_b, const float* __restrict__ dw_w,
    float* __restrict__ dwout)
{
    __shared__ float sdw[RB * 256];
    __shared__ float sband[RB * IBND];
    __shared__ float ssum[RB];
    __shared__ float xs[2][16 * 256];

    const int tid = threadIdx.x;
    const int b = blockIdx.x >> 4;
    const int i = blockIdx.x & 15;

    for (int l = tid; l < RB * 256; l += 512)  sdw[l]   = dw_w[l];
    for (int l = tid; l < RB * IBND; l += 512) sband[l] = band_w[l];
    __syncthreads();
    if (tid < RB) {
        float s = 0.f;
        for (int u = 0; u < 256; u++) s += sdw[tid * 256 + u];
        ssum[tid] = s;
    }

    const int w  = tid & 255;
    const int ch = tid >> 8;
    const int wq = w & 15;
    const int j  = w >> 4;

    float wt[4][16];
#pragma unroll
    for (int cl = 0; cl < 4; cl++)
#pragma unroll
        for (int p = 0; p < 16; p++)
            wt[cl][p] = sdw[((ch * 4 + cl) * 16 + p) * 16 + wq];
    __syncthreads();

    const int lin  = tid * 8;
    const int lrow = lin >> 8;
    const int lcol = lin & 255;

    float D[4] = {0.f, 0.f, 0.f, 0.f};
    float4 f0, f1;
    {
        const float* px = x + (((size_t)(b * IBND + 0) * HWD + i * 16 + lrow) * HWD + lcol);
        f0 = ((const float4*)px)[0];
        f1 = ((const float4*)px)[1];
    }

    for (int ib = 0; ib < IBND; ib++) {
        float* sdst = &xs[ib & 1][lrow * 256 + lcol];
        ((float4*)sdst)[0] = f0;
        ((float4*)sdst)[1] = f1;
        __syncthreads();

        if (ib + 1 < IBND) {
            const float* px = x + (((size_t)(b * IBND + ib + 1) * HWD + i * 16 + lrow) * HWD + lcol);
            f0 = ((const float4*)px)[0];
            f1 = ((const float4*)px)[1];
        }

        const float* xc = &xs[ib & 1][0];
        float s0 = 0.f, s1 = 0.f, s2 = 0.f, s3 = 0.f;
#pragma unroll
        for (int p = 0; p < 16; p++) {
            float xv = xc[p * 256 + w];
            s0 += xv * wt[0][p];
            s1 += xv * wt[1][p];
            s2 += xv * wt[2][p];
            s3 += xv * wt[3][p];
        }
        const int cb = ch * 4;
        D[0] += sband[(cb + 0) * IBND + ib] * s0;
        D[1] += sband[(cb + 1) * IBND + ib] * s1;
        D[2] += sband[(cb + 2) * IBND + ib] * s2;
        D[3] += sband[(cb + 3) * IBND + ib] * s3;
        __syncthreads();
    }

#pragma unroll
    for (int cl = 0; cl < 4; cl++) {
        float v = D[cl];
        v += __shfl_down_sync(0xffffffffu, v, 8, 16);
        v += __shfl_down_sync(0xffffffffu, v, 4, 16);
        v += __shfl_down_sync(0xffffffffu, v, 2, 16);
        v += __shfl_down_sync(0xffffffffu, v, 1, 16);
        if (wq == 0) {
            int c = ch * 4 + cl;
            dwout[((b * RB + c) * 16 + i) * 16 + j] = v + band_b[c] * ssum[c];
        }
    }
}

// ---------------- 192-thread block reduction helper ----------------
__device__ __forceinline__ float blk_sum_192(float v, float* sb) {
#pragma unroll
    for (int o = 16; o; o >>= 1) v += __shfl_down_sync(0xffffffffu, v, o);
    __syncthreads();
    if ((threadIdx.x & 31) == 0) sb[threadIdx.x >> 5] = v;
    __syncthreads();
    if (threadIdx.x == 0)
        sb[6] = sb[0] + sb[1] + sb[2] + sb[3] + sb[4] + sb[5];
    __syncthreads();
    return sb[6];
}

// ============================================================
// Kernel 2: pointwise 8->192 conv + LayerNorm -> tok, xb
// ============================================================
__global__ void k_pw_ln(const float* __restrict__ dw, const float* __restrict__ pw_w,
                        const float* __restrict__ lw, const float* __restrict__ lb,
                        float* __restrict__ tok, float* __restrict__ xbuf)
{
    const int row = blockIdx.x;
    const int b = row >> 8, n = row & 255;
    const int d = threadIdx.x;
    __shared__ float sdwv[RB];
    __shared__ float sb[8];
    if (d < RB) sdwv[d] = dw[((size_t)b * RB + d) * NTOK + n];
    __syncthreads();
    float t = 0.f;
#pragma unroll
    for (int c = 0; c < RB; c++) t += sdwv[c] * pw_w[d * RB + c];
    float mean = blk_sum_192(t, sb) * (1.f / 192.f);
    float dv = t - mean;
    float var = blk_sum_192(dv * dv, sb) * (1.f / 192.f);
    float o = dv * rsqrtf(var + 1e-5f) * lw[d] + lb[d];
    size_t idx = (size_t)row * DIM + d;
    tok[idx] = o;
    xbuf[idx] = o;
}

// ============================================================
// row stats: LN (mean, rstd) — warp per row, 8 rows/block
// ============================================================
__global__ void __launch_bounds__(256) k_lnstats(const float* __restrict__ xin,
                                                 float* __restrict__ s0, float* __restrict__ s1)
{
    const int warp = threadIdx.x >> 5, lane = threadIdx.x & 31;
    const int row = blockIdx.x * 8 + warp;
    const float* p = xin + (size_t)row * DIM;
    float v[6];
#pragma unroll
    for (int j = 0; j < 6; j++) v[j] = p[lane + j * 32];
    float s = v[0] + v[1] + v[2] + v[3] + v[4] + v[5];
#pragma unroll
    for (int o = 16; o; o >>= 1) s += __shfl_xor_sync(0xffffffffu, s, o);
    float mu = s * (1.f / 192.f);
    float q = 0.f;
#pragma unroll
    for (int j = 0; j < 6; j++) { float d = v[j] - mu; q += d * d; }
#pragma unroll
    for (int o = 16; o; o >>= 1) q += __shfl_xor_sync(0xffffffffu, q, o);
    if (lane == 0) { s0[row] = mu; s1[row] = rsqrtf(q * (1.f / 192.f) + 1e-5f); }
}

// ============================================================
// row stats: softmax (max, 1/sum(exp(x-max)))
// ============================================================
__global__ void __launch_bounds__(256) k_smstats(const float* __restrict__ xin,
                                                 float* __restrict__ s0, float* __restrict__ s1)
{
    const int warp = threadIdx.x >> 5, lane = threadIdx.x & 31;
    const int row = blockIdx.x * 8 + warp;
    const float* p = xin + (size_t)row * DIM;
    float v[6];
#pragma unroll
    for (int j = 0; j < 6; j++) v[j] = p[lane + j * 32];
    float m = v[0];
#pragma unroll
    for (int j = 1; j < 6; j++) m = fmaxf(m, v[j]);
#pragma unroll
    for (int o = 16; o; o >>= 1) m = fmaxf(m, __shfl_xor_sync(0xffffffffu, m, o));
    float e = 0.f;
#pragma unroll
    for (int j = 0; j < 6; j++) e += expf(v[j] - m);
#pragma unroll
    for (int o = 16; o; o >>= 1) e += __shfl_xor_sync(0xffffffffu, e, o);
    if (lane == 0) { s0[row] = m; s1[row] = 1.f / e; }
}

// ============================================================
// router top-2 + gates + prototype mixing -> cat[row, 200]
// ============================================================
__global__ void k_mix(const float* __restrict__ rl, const float* __restrict__ spec_proto,
                      const float* __restrict__ spat_proto, float* __restrict__ cat)
{
    const int row = blockIdx.x;
    const int d = threadIdx.x;
    __shared__ float srl[48];
    __shared__ float sg[4];
    __shared__ int   sidx[4];
    if (d < 48) srl[d] = rl[(size_t)row * 48 + d];
    __syncthreads();
    if (d < 2) {
        const float* base = srl + d * 24;
        float m1 = -1e30f; int i1 = 0;
        for (int k = 0; k < 24; k++) if (base[k] > m1) { m1 = base[k]; i1 = k; }
        float m2 = -1e30f; int i2 = 0;
        for (int k = 0; k < 24; k++) if (k != i1 && base[k] > m2) { m2 = base[k]; i2 = k; }
        float e  = expf((m2 - m1) / TAUV);
        float iv = 1.f / (1.f + e);
        sg[d * 2] = iv; sg[d * 2 + 1] = e * iv;
        sidx[d * 2] = i1; sidx[d * 2 + 1] = i2;
    }
    __syncthreads();
    float* crow = cat + (size_t)row * 200;
    if (d < RB)
        crow[d] = sg[0] * spec_proto[sidx[0] * RB + d] + sg[1] * spec_proto[sidx[1] * RB + d];
    crow[8 + d] = sg[2] * spat_proto[sidx[2] * DIM + d] + sg[3] * spat_proto[sidx[3] * DIM + d];
}

// ============================================================
// exact fp32 GEMM, 64x64 tile, BK=16, 256 thr, 4x4/thread (router only)
// EPI: 1 = +bias, 2 = gelu(+bias)
// ============================================================
template <int EPI>
__global__ void __launch_bounds__(256) gemm64(
    const float* __restrict__ A, const float* __restrict__ B,
    float* __restrict__ C, const float* __restrict__ bias,
    int M, int N, int K)
{
    __shared__ float As[16][68];
    __shared__ float Bs[16][68];
    const int m0 = blockIdx.y * 64, n0 = blockIdx.x * 64;
    const int tid = threadIdx.x;
    const int ty = tid >> 4, tx = tid & 15;
    const int am = tid >> 2, ak = (tid & 3) * 4;
    const int bk = tid >> 4, bn = (tid & 15) * 4;

    float acc[4][4];
#pragma unroll
    for (int i = 0; i < 4; i++)
#pragma unroll
        for (int jj = 0; jj < 4; jj++) acc[i][jj] = 0.f;

    for (int k0 = 0; k0 < K; k0 += 16) {
        {
            float4 t = make_float4(0.f, 0.f, 0.f, 0.f);
            int gm = m0 + am, gk = k0 + ak;
            if (gm < M && gk + 3 < K) t = *(const float4*)(A + (size_t)gm * K + gk);
            As[ak + 0][am] = t.x; As[ak + 1][am] = t.y;
            As[ak + 2][am] = t.z; As[ak + 3][am] = t.w;
        }
        {
            float4 t = make_float4(0.f, 0.f, 0.f, 0.f);
            int gk = k0 + bk, gn = n0 + bn;
            if (gk < K) {
                if (gn + 3 < N) t = *(const float4*)(B + (size_t)gk * N + gn);
                else {
                    float* tp = (float*)&t;
                    for (int u = 0; u < 4; u++)
                        if (gn + u < N) tp[u] = B[(size_t)gk * N + gn + u];
                }
            }
            *(float4*)&Bs[bk][bn] = t;
        }
        __syncthreads();
#pragma unroll
        for (int kk = 0; kk < 16; kk++) {
            float4 a = *(const float4*)&As[kk][ty * 4];
            float4 b = *(const float4*)&Bs[kk][tx * 4];
            float am4[4] = {a.x, a.y, a.z, a.w};
            float bm4[4] = {b.x, b.y, b.z, b.w};
#pragma unroll
            for (int i = 0; i < 4; i++)
#pragma unroll
                for (int jj = 0; jj < 4; jj++) acc[i][jj] += am4[i] * bm4[jj];
        }
        __syncthreads();
    }
#pragma unroll
    for (int i = 0; i < 4; i++) {
        int row = m0 + ty * 4 + i;
        if (row >= M) continue;
#pragma unroll
        for (int jj = 0; jj < 4; jj++) {
            int col = n0 + tx * 4 + jj;
            if (col >= N) continue;
            float v = acc[i][jj];
            if (EPI == 1) C[(size_t)row * N + col] = v + bias[col];
            else          C[(size_t)row * N + col] = geluf(v + bias[col]);
        }
    }
}

// ============================================================
// tf32 tensor-core GEMM v2 with register prefetch + fused A-transforms.
// BM=128, BN=64, BK=32, 256 thr = 8 warps (4m x 2n), warp tile 32x32.
// Logical k permutation: mma step ks, lane l -> phys k = 8ks + 2(l&3) + (l>>2)
//   => A fragments are LDS.64 pairs from natural row-major smem.
// TRANSA=0: A MxK row-major.  TRANSA=1: A KxM row-major (A^T @ B).
// ATR: 0 none, 1 LayerNorm (s0=mean, s1=rstd, tw/tb), 2 softmax (s0=max, s1=1/sum)
// EPI: 0 store, 1 +bias, 2 gelu(+bias), 3 C += acc*scale, 4 C += (acc+bias)*scale
// Column split: blockIdx.x >= xsplit uses B2/C2 (merged q/v launch).
// ============================================================
#define SA0 40
#define SA1 132
#define SBP 68

template <int EPI, int TRANSA, int ATR>
__global__ void __launch_bounds__(256) mma2(
    const float* __restrict__ A, const float* __restrict__ B, const float* __restrict__ B2,
    float* __restrict__ C, float* __restrict__ C2, int xsplit,
    const float* __restrict__ bias, const float* __restrict__ scale,
    const float* __restrict__ s0, const float* __restrict__ s1,
    const float* __restrict__ tw, const float* __restrict__ tb,
    int M, int N, int K, long sAs, long sBs, long sCs, int statStride)
{
    __shared__ float sA[128 * SA0];   // 5120 floats (TRANSA=1 uses 32*132=4224 of it)
    __shared__ float sB[32 * SBP];    // 2176 floats

    const long bz = blockIdx.z;
    const float* Ap = A + bz * sAs;
    const float* Bp = (blockIdx.x < xsplit ? B : B2) + bz * sBs;
    float*       Cp = (blockIdx.x < xsplit ? C : C2) + bz * sCs;
    const int m0 = blockIdx.y * 128;
    const int n0 = (blockIdx.x % xsplit) * 64;
    const int tid = threadIdx.x;
    const int warp = tid >> 5, lane = tid & 31;
    const int grp = lane >> 2, tig = lane & 3;
    const int wm = warp >> 1, wn = warp & 1;

    float acc[2][4][4];
#pragma unroll
    for (int mt = 0; mt < 2; mt++)
#pragma unroll
        for (int nt = 0; nt < 4; nt++)
#pragma unroll
            for (int e = 0; e < 4; e++) acc[mt][nt][e] = 0.f;

    float4 apre[4];
    float4 bpre[2];

    // ---------- fetch helpers (to registers) ----------
    auto fetchA = [&](int k0) {
#pragma unroll
        for (int it = 0; it < 4; it++) {
            int id = tid + it * 256;
            float4 t = make_float4(0.f, 0.f, 0.f, 0.f);
            if (TRANSA == 0) {
                int m = id >> 3, k4 = (id & 7) * 4;
                int gm = m0 + m, gk = k0 + k4;
                if (gm < M && gk < K) {
                    if (gk + 3 < K) t = *(const float4*)(Ap + (size_t)gm * K + gk);
                    else {
                        float* tp = (float*)&t;
#pragma unroll
                        for (int u = 0; u < 4; u++)
                            if (gk + u < K) tp[u] = Ap[(size_t)gm * K + gk + u];
                    }
                }
                if (ATR == 1 && gm < M) {
                    int sr = (int)bz * statStride + gm;
                    float mu = s0[sr], rs = s1[sr];
                    float4 w4 = make_float4(0.f, 0.f, 0.f, 0.f);
                    float4 b4 = make_float4(0.f, 0.f, 0.f, 0.f);
                    if (gk + 3 < K) { w4 = *(const float4*)(tw + gk); b4 = *(const float4*)(tb + gk); }
                    t.x = (t.x - mu) * rs * w4.x + b4.x;
                    t.y = (t.y - mu) * rs * w4.y + b4.y;
                    t.z = (t.z - mu) * rs * w4.z + b4.z;
                    t.w = (t.w - mu) * rs * w4.w + b4.w;
                }
                if (ATR == 2 && gm < M) {
                    int sr = (int)bz * statStride + gm;
                    float mx = s0[sr], iv = s1[sr];
                    t.x = expf(t.x - mx) * iv;
                    t.y = expf(t.y - mx) * iv;
                    t.z = expf(t.z - mx) * iv;
                    t.w = expf(t.w - mx) * iv;
                }
            } else {
                int k = id >> 5, m4 = (id & 31) * 4;
                int gk = k0 + k, gm = m0 + m4;
                if (gk < K && gm < M) {
                    if (gm + 3 < M) t = *(const float4*)(Ap + (size_t)gk * M + gm);
                    else {
                        float* tp = (float*)&t;
#pragma unroll
                        for (int u = 0; u < 4; u++)
                            if (gm + u < M) tp[u] = Ap[(size_t)gk * M + gm + u];
                    }
                }
            }
            apre[it] = t;
        }
    };
    auto fetchB = [&](int k0) {
#pragma unroll
        for (int it = 0; it < 2; it++) {
            int id = tid + it * 256;
            int k = id >> 4, n4 = (id & 15) * 4;
            int gk = k0 + k, gn = n0 + n4;
            float4 t = make_float4(0.f, 0.f, 0.f, 0.f);
            if (gk < K) {
                if (gn + 3 < N) t = *(const float4*)(Bp + (size_t)gk * N + gn);
                else {
                    float* tp = (float*)&t;
#pragma unroll
                    for (int u = 0; u < 4; u++)
                        if (gn + u < N) tp[u] = Bp[(size_t)gk * N + gn + u];
                }
            }
            bpre[it] = t;
        }
    };
    auto storeA = [&]() {
#pragma unroll
        for (int it = 0; it < 4; it++) {
            int id = tid + it * 256;
            uint4 c;
            c.x = to_tf32(apre[it].x); c.y = to_tf32(apre[it].y);
            c.z = to_tf32(apre[it].z); c.w = to_tf32(apre[it].w);
            if (TRANSA == 0) {
                int m = id >> 3, k4 = (id & 7) * 4;
                *(uint4*)&sA[m * SA0 + k4] = c;
            } else {
                int k = id >> 5, m4 = (id & 31) * 4;
                *(uint4*)&sA[k * SA1 + m4] = c;
            }
        }
    };
    auto storeB = [&]() {
#pragma unroll
        for (int it = 0; it < 2; it++) {
            int id = tid + it * 256;
            int k = id >> 4, n4 = (id & 15) * 4;
            uint4 c;
            c.x = to_tf32(bpre[it].x); c.y = to_tf32(bpre[it].y);
            c.z = to_tf32(bpre[it].z); c.w = to_tf32(bpre[it].w);
            *(uint4*)&sB[k * SBP + n4] = c;
        }
    };

    // ---------- main loop with register prefetch ----------
    fetchA(0); fetchB(0);
    storeA(); storeB();
    __syncthreads();

    const int T = (K + 31) / 32;
    for (int t = 0; ; t++) {
        const bool more = (t + 1) < T;
        if (more) { fetchA((t + 1) * 32); fetchB((t + 1) * 32); }

#pragma unroll
        for (int ks = 0; ks < 4; ks++) {
            uint32_t a[2][4], b[4][2];
            const int kr = ks * 8 + tig * 2;
#pragma unroll
            for (int mt = 0; mt < 2; mt++) {
                int mr = wm * 32 + mt * 16 + grp;
                if (TRANSA == 0) {
                    float2 p0 = *(const float2*)&sA[mr * SA0 + kr];
                    float2 p1 = *(const float2*)&sA[(mr + 8) * SA0 + kr];
                    a[mt][0] = __float_as_uint(p0.x);
                    a[mt][1] = __float_as_uint(p1.x);
                    a[mt][2] = __float_as_uint(p0.y);
                    a[mt][3] = __float_as_uint(p1.y);
                } else {
                    a[mt][0] = __float_as_uint(sA[kr * SA1 + mr]);
                    a[mt][2] = __float_as_uint(sA[(kr + 1) * SA1 + mr]);
                    a[mt][1] = __float_as_uint(sA[kr * SA1 + mr + 8]);
                    a[mt][3] = __float_as_uint(sA[(kr + 1) * SA1 + mr + 8]);
                }
            }
#pragma unroll
            for (int nt = 0; nt < 4; nt++) {
                int nc = wn * 32 + nt * 8 + grp;
                b[nt][0] = __float_as_uint(sB[kr * SBP + nc]);
                b[nt][1] = __float_as_uint(sB[(kr + 1) * SBP + nc]);
            }
#pragma unroll
            for (int mt = 0; mt < 2; mt++)
#pragma unroll
                for (int nt = 0; nt < 4; nt++)
                    mma_tf32(acc[mt][nt], a[mt], b[nt]);
        }

        if (!more) break;
        __syncthreads();
        storeA(); storeB();
        __syncthreads();
    }

    // ---------- epilogue ----------
#pragma unroll
    for (int mt = 0; mt < 2; mt++) {
        int r0 = m0 + wm * 32 + mt * 16 + grp;
#pragma unroll
        for (int nt = 0; nt < 4; nt++) {
            int c0 = n0 + wn * 32 + nt * 8 + tig * 2;
            const float* ap = acc[mt][nt];
#pragma unroll
            for (int e = 0; e < 4; e++) {
                int row = r0 + (e >= 2 ? 8 : 0);
                int col = c0 + (e & 1);
                if (row >= M || col >= N) continue;
                float v = ap[e];
                size_t idx = (size_t)row * N + col;
                if (EPI == 0)      Cp[idx] = v;
                else if (EPI == 1) Cp[idx] = v + bias[col];
                else if (EPI == 2) Cp[idx] = geluf(v + bias[col]);
                else if (EPI == 3) Cp[idx] = Cp[idx] + v * scale[col];
                else if (EPI == 4) Cp[idx] = Cp[idx] + (v + bias[col]) * scale[col];
            }
        }
    }
}

// ============================================================
// final: feat = LN(mean_n xb), out = feat @ head_w + head_b
// ============================================================
__global__ void k_final(const float* __restrict__ xb,
                        const float* __restrict__ lw, const float* __restrict__ lb,
                        const float* __restrict__ hw, const float* __restrict__ hb,
                        float* __restrict__ out)
{
    const int b = blockIdx.x, d = threadIdx.x;
    __shared__ float sfeat[DIM];
    __shared__ float sb[8];
    const float* base = xb + (size_t)b * NTOK * DIM;
    float acc = 0.f;
    for (int n = 0; n < NTOK; n++) acc += base[n * DIM + d];
    float m = acc * (1.f / 256.f);
    float mean = blk_sum_192(m, sb) * (1.f / 192.f);
    float dv = m - mean;
    float var = blk_sum_192(dv * dv, sb) * (1.f / 192.f);
    sfeat[d] = dv * rsqrtf(var + 1e-5f) * lw[d] + lb[d];
    __syncthreads();
    if (d < NC) {
        float o = hb[d];
        for (int e = 0; e < DIM; e++) o += sfeat[e] * hw[e * NC + d];
        out[b * NC + d] = o;
    }
}

// ============================================================
extern "C" void kernel_launch(void* const* d_in, const int* in_sizes, int n_in,
                              void* d_out, int out_size)
{
    const float* x        = (const float*)d_in[0];
    const float* band_w   = (const float*)d_in[1];
    const float* band_b   = (const float*)d_in[2];
    const float* dw_w     = (const float*)d_in[3];
    const float* pw_w     = (const float*)d_in[4];
    const float* pe_ln_w  = (const float*)d_in[5];
    const float* pe_ln_b  = (const float*)d_in[6];
    const float* spec_pr  = (const float*)d_in[7];
    const float* spat_pr  = (const float*)d_in[8];
    const float* r1_w     = (const float*)d_in[9];
    const float* r1_b     = (const float*)d_in[10];
    const float* r2_w     = (const float*)d_in[11];
    const float* r2_b     = (const float*)d_in[12];
    const float* key_w    = (const float*)d_in[13];
    const float* pos_bias = (const float*)d_in[14];
    const float* bln_w    = (const float*)d_in[15];
    const float* bln_b    = (const float*)d_in[16];
    const float* bq_w     = (const float*)d_in[17];
    const float* bv_w     = (const float*)d_in[18];
    const float* bf1_w    = (const float*)d_in[19];
    const float* bf1_b    = (const float*)d_in[20];
    const float* bf2_w    = (const float*)d_in[21];
    const float* bf2_b    = (const float*)d_in[22];
    const float* bg1      = (const float*)d_in[23];
    const float* bg2      = (const float*)d_in[24];
    const float* fin_ln_w = (const float*)d_in[25];
    const float* fin_ln_b = (const float*)d_in[26];
    const float* head_w   = (const float*)d_in[27];
    const float* head_b   = (const float*)d_in[28];
    float* out = (float*)d_out;

    float *dw, *tok, *xb, *h, *rl, *cat, *keys, *q, *v, *kv, *ff, *st0, *st1;
    cudaGetSymbolAddress((void**)&dw,   g_dw);
    cudaGetSymbolAddress((void**)&tok,  g_tok);
    cudaGetSymbolAddress((void**)&xb,   g_xb);
    cudaGetSymbolAddress((void**)&h,    g_h);
    cudaGetSymbolAddress((void**)&rl,   g_rl);
    cudaGetSymbolAddress((void**)&cat,  g_cat);
    cudaGetSymbolAddress((void**)&keys, g_keys);
    cudaGetSymbolAddress((void**)&q,    g_q);
    cudaGetSymbolAddress((void**)&v,    g_v);
    cudaGetSymbolAddress((void**)&kv,   g_kv);
    cudaGetSymbolAddress((void**)&ff,   g_ff);
    cudaGetSymbolAddress((void**)&st0,  g_s0);
    cudaGetSymbolAddress((void**)&st1,  g_s1);

    const int BIG = 1 << 20;
    const long sTok = (long)NTOK * DIM;
    const long sKV  = (long)DIM * DIM;

    // 1. fused band + depthwise conv
    k_band_dw<<<NB * 16, 512>>>(x, band_w, band_b, dw_w, dw);
    // 2. pointwise conv + LN -> tok, xb
    k_pw_ln<<<NROW, DIM>>>(dw, pw_w, pe_ln_w, pe_ln_b, tok, xb);
    // 3. router MLP (exact fp32 — protects top-k index selection)
    gemm64<2><<<dim3(2, 128), 256>>>(tok, r1_w, h, r1_b, NROW, 128, DIM);
    gemm64<1><<<dim3(1, 128), 256>>>(h, r2_w, rl, r2_b, NROW, 48, 128);
    // 4. top-2 gates + prototype mix -> cat[.,200]
    k_mix<<<NROW, DIM>>>(rl, spec_pr, spat_pr, cat);
    // 5. keys = cat @ key_w + pos_bias  (tf32)
    mma2<1, 0, 0><<<dim3(3, 64), 256>>>(cat, key_w, nullptr, keys, nullptr, BIG,
                                        pos_bias, nullptr, nullptr, nullptr, nullptr, nullptr,
                                        NROW, DIM, 200, 0, 0, 0, 0);

    for (int i = 0; i < 3; i++) {
        const float* lwi = bln_w + i * DIM;
        const float* lbi = bln_b + i * DIM;
        // LN stats of xb, then merged q+v GEMM with fused LN on A
        k_lnstats<<<NROW / 8, 256>>>(xb, st0, st1);
        mma2<0, 0, 1><<<dim3(6, 64), 256>>>(xb, bq_w + (size_t)i * DIM * DIM, bv_w + (size_t)i * DIM * DIM,
                                            q, v, 3, nullptr, nullptr, st0, st1, lwi, lbi,
                                            NROW, DIM, DIM, 0, 0, 0, 0);
        // softmax stats of q
        k_smstats<<<NROW / 8, 256>>>(q, st0, st1);
        // KV[b] = keys[b]^T @ v[b]
        mma2<0, 1, 0><<<dim3(3, 2, NB), 256>>>(keys, v, nullptr, kv, nullptr, BIG,
                                               nullptr, nullptr, nullptr, nullptr, nullptr, nullptr,
                                               DIM, DIM, NTOK, sTok, sTok, sKV, 0);
        // xb += (softmax(q) @ KV) * g1   (softmax fused into A-load)
        mma2<3, 0, 2><<<dim3(3, 2, NB), 256>>>(q, kv, nullptr, xb, nullptr, BIG,
                                               nullptr, bg1 + i * DIM, st0, st1, nullptr, nullptr,
                                               NTOK, DIM, DIM, sTok, sKV, sTok, NTOK);
        // FFN: LN stats, f1 with fused LN + gelu, f2 with residual
        k_lnstats<<<NROW / 8, 256>>>(xb, st0, st1);
        mma2<2, 0, 1><<<dim3(6, 64), 256>>>(xb, bf1_w + (size_t)i * DIM * FFH, nullptr,
                                            ff, nullptr, BIG, bf1_b + i * FFH, nullptr, st0, st1, lwi, lbi,
                                            NROW, FFH, DIM, 0, 0, 0, 0);
        mma2<4, 0, 0><<<dim3(3, 64), 256>>>(ff, bf2_w + (size_t)i * FFH * DIM, nullptr,
                                            xb, nullptr, BIG, bf2_b + i * DIM, bg2 + i * DIM,
                                            nullptr, nullptr, nullptr, nullptr,
                                            NROW, DIM, FFH, 0, 0, 0, 0);
    }

    // final pooling + LN + head
    k_final<<<NB, DIM>>>(xb, fin_ln_w, fin_ln_b, head_w, head_b, out);

    (void)in_sizes; (void)n_in; (void)out_size;
}